// round 1
// baseline (speedup 1.0000x reference)
#include <cuda_runtime.h>
#include <math.h>

#define N_NODES 10000
#define N_EDGES 100000
#define F_NODE 128
#define F_EDGE 16
#define HEADS 8
#define OUT_CH 128
#define HC 1024  // HEADS*OUT_CH

// ---------------- scratch (device globals; no runtime allocation) ----------------
__device__ float d_q[N_NODES * HC];
__device__ float d_k[N_NODES * HC];
__device__ float d_v[N_NODES * HC];
__device__ float d_skip[N_NODES * OUT_CH];
__device__ float d_g[N_NODES * 128];       // g[n, h*16+f] = sum_c q[n,h,c]*We[f,h,c]
__device__ float d_aexp[N_EDGES * HEADS];  // exp(alpha)
__device__ float d_s[N_NODES * HEADS];     // softmax denominators
__device__ float d_vout[N_NODES * OUT_CH]; // v-term accumulation (head-mean folded)
__device__ float d_B[N_NODES * 128];       // B[n, h*16+f] = sum_e alpha_n*ea
__device__ float d_eterm[N_NODES * OUT_CH];
__device__ float d_Wer[128 * 128];         // Wer[h*16+f][c] = We[f, h*128+c]
__device__ float d_zero_bias[1024];        // static zeros
__device__ float d_pooled[OUT_CH];

// ---------------- init ----------------
__global__ void init_kernel() {
    int i = blockIdx.x * 256 + threadIdx.x;
    if (i < N_NODES * 128) { d_vout[i] = 0.f; d_B[i] = 0.f; }
    if (i < N_NODES * HEADS) d_s[i] = 0.f;
    if (i < OUT_CH) d_pooled[i] = 0.f;
}

// ---------------- GEMM: C[M,N] = A[M,128] @ W[128,N] + bias[N] ----------------
// BM=128, BN=128, BK=16, 256 threads, 8x8 microtile.
// mode==1: A=d_B, W=d_Wer, bias=d_zero_bias (eterm GEMM).
// out_sel: 0=d_q 1=d_k 2=d_v 3=d_skip 4=d_eterm
__global__ __launch_bounds__(256) void gemm_bias_kernel(
    const float* __restrict__ A, const float* __restrict__ W,
    const float* __restrict__ bias, int out_sel, int mode, int M, int N) {
    if (mode == 1) { A = d_B; W = d_Wer; bias = d_zero_bias; }
    float* C = (out_sel == 0) ? d_q : (out_sel == 1) ? d_k : (out_sel == 2) ? d_v
             : (out_sel == 3) ? d_skip : d_eterm;

    __shared__ float As[16][132];   // [k][m], padded
    __shared__ float Bs[16][128];   // [k][n]
    const int K = 128;
    int tid = threadIdx.x;
    int bm = blockIdx.y * 128, bn = blockIdx.x * 128;
    int ty = tid >> 4, tx = tid & 15;
    float acc[8][8];
#pragma unroll
    for (int i = 0; i < 8; i++)
#pragma unroll
        for (int j = 0; j < 8; j++) acc[i][j] = 0.f;

    int ar = tid >> 2;          // 0..63
    int ac = (tid & 3) * 4;     // k offset (float4)
    int wn = (tid & 31) * 4;    // n offset (float4)
    int wk = tid >> 5;          // 0..7

    for (int kc = 0; kc < K; kc += 16) {
#pragma unroll
        for (int p = 0; p < 2; p++) {
            int row = bm + ar + p * 64;
            float4 av = make_float4(0.f, 0.f, 0.f, 0.f);
            if (row < M) av = *(const float4*)&A[row * K + kc + ac];
            As[ac + 0][ar + p * 64] = av.x;
            As[ac + 1][ar + p * 64] = av.y;
            As[ac + 2][ar + p * 64] = av.z;
            As[ac + 3][ar + p * 64] = av.w;
        }
#pragma unroll
        for (int p = 0; p < 2; p++) {
            int kr = wk + p * 8;
            *(float4*)&Bs[kr][wn] = *(const float4*)&W[(kc + kr) * N + bn + wn];
        }
        __syncthreads();
#pragma unroll
        for (int kk = 0; kk < 16; kk++) {
            float a[8], b[8];
            *(float4*)&a[0] = *(float4*)&As[kk][ty * 8];
            *(float4*)&a[4] = *(float4*)&As[kk][ty * 8 + 4];
            *(float4*)&b[0] = *(float4*)&Bs[kk][tx * 8];
            *(float4*)&b[4] = *(float4*)&Bs[kk][tx * 8 + 4];
#pragma unroll
            for (int i = 0; i < 8; i++)
#pragma unroll
                for (int j = 0; j < 8; j++) acc[i][j] += a[i] * b[j];
        }
        __syncthreads();
    }
#pragma unroll
    for (int i = 0; i < 8; i++) {
        int row = bm + ty * 8 + i;
        if (row < M) {
#pragma unroll
            for (int j = 0; j < 8; j += 4) {
                int col = bn + tx * 8 + j;
                float4 o;
                o.x = acc[i][j + 0] + bias[col + 0];
                o.y = acc[i][j + 1] + bias[col + 1];
                o.z = acc[i][j + 2] + bias[col + 2];
                o.w = acc[i][j + 3] + bias[col + 3];
                *(float4*)&C[row * N + col] = o;
            }
        }
    }
}

// ---------------- build We_r[j][c] = We[f, h*128+c], j=h*16+f ----------------
__global__ void build_wer(const float* __restrict__ We) {
    int idx = blockIdx.x * 256 + threadIdx.x;
    if (idx < 128 * 128) {
        int j = idx >> 7, c = idx & 127;
        int h = j >> 4, f = j & 15;
        d_Wer[idx] = We[f * HC + h * 128 + c];
    }
}

// ---------------- g[n, j] = sum_c We_r[j][c] * q[n, (j/16)*128 + c] ----------------
// 128 threads: 2 nodes x 64 j per iteration. Launched twice (joff 0, 64).
__global__ __launch_bounds__(128) void g_kernel(const float* __restrict__ We, int joff) {
    __shared__ float sW[128][65];   // [c][jl]
    __shared__ float sq[2][HC];
    for (int i = threadIdx.x; i < 128 * 64; i += 128) {
        int c = i >> 6, jl = i & 63;
        int j = joff + jl, h = j >> 4, f = j & 15;
        sW[c][jl] = We[f * HC + h * 128 + c];
    }
    int jl = threadIdx.x & 63;
    int nn = threadIdx.x >> 6;
    int h = (joff + jl) >> 4;
    for (int n0 = blockIdx.x * 2; n0 < N_NODES; n0 += gridDim.x * 2) {
        __syncthreads();
        for (int i = threadIdx.x; i < 2 * HC; i += 128) {
            int nn2 = i / HC, cc = i % HC;
            int n = n0 + nn2;
            sq[nn2][cc] = (n < N_NODES) ? d_q[n * HC + cc] : 0.f;
        }
        __syncthreads();
        int n = n0 + nn;
        float acc = 0.f;
        const float* qh = &sq[nn][h * 128];
#pragma unroll 8
        for (int c = 0; c < 128; c++) acc += sW[c][jl] * qh[c];
        if (n < N_NODES) d_g[n * 128 + joff + jl] = acc;
    }
}

// ---------------- edge pass A: alpha -> exp -> atomic sum ----------------
__global__ __launch_bounds__(256) void edge_alpha(const float* __restrict__ ea,
                                                  const int* __restrict__ eidx) {
    int e = blockIdx.x * 8 + threadIdx.y;
    if (e >= N_EDGES) return;
    int lane = threadIdx.x;
    int src = eidx[e];
    int dst = eidx[N_EDGES + e];
    const float4* q4 = (const float4*)&d_q[dst * HC];
    const float4* k4 = (const float4*)&d_k[src * HC];
    float myalpha = 0.f;
#pragma unroll
    for (int h = 0; h < 8; h++) {
        float4 a = q4[h * 32 + lane];
        float4 b = k4[h * 32 + lane];
        float dp = a.x * b.x + a.y * b.y + a.z * b.z + a.w * b.w;
#pragma unroll
        for (int o = 16; o; o >>= 1) dp += __shfl_xor_sync(0xffffffffu, dp, o);
        if (lane == h) myalpha = dp;
    }
    if (lane < 8) {
        float et = 0.f;
        const float* gp = &d_g[dst * 128 + lane * 16];
        const float* eap = &ea[e * F_EDGE];
#pragma unroll
        for (int f = 0; f < 16; f++) et += eap[f] * gp[f];
        float alpha = (myalpha + et) * 0.08838834764831845f;  // 1/sqrt(128)
        float aex = expf(alpha);
        d_aexp[e * 8 + lane] = aex;
        atomicAdd(&d_s[dst * 8 + lane], aex);
    }
}

// ---------------- edge pass B: v-term scatter + B-coefficient scatter ----------------
__global__ __launch_bounds__(256) void edge_msg(const float* __restrict__ ea,
                                                const int* __restrict__ eidx) {
    int e = blockIdx.x * 8 + threadIdx.y;
    if (e >= N_EDGES) return;
    int lane = threadIdx.x;
    int src = eidx[e];
    int dst = eidx[N_EDGES + e];
    float an = 0.f;
    if (lane < 8) {
        float s = d_s[dst * 8 + lane];
        an = 0.125f * d_aexp[e * 8 + lane] / (s + 1e-16f);  // head-mean folded
    }
    float eaf = 0.f;
    if (lane < 16) eaf = ea[e * F_EDGE + lane];
    float my_ea = __shfl_sync(0xffffffffu, eaf, lane & 15);

    const float4* v4 = (const float4*)&d_v[src * HC];
    float4 acc = make_float4(0.f, 0.f, 0.f, 0.f);
#pragma unroll
    for (int h = 0; h < 8; h++) {
        float anh = __shfl_sync(0xffffffffu, an, h);
        float4 vv = v4[h * 32 + lane];
        acc.x += anh * vv.x;
        acc.y += anh * vv.y;
        acc.z += anh * vv.z;
        acc.w += anh * vv.w;
    }
    float* outp = &d_vout[dst * 128 + lane * 4];
    atomicAdd(outp + 0, acc.x);
    atomicAdd(outp + 1, acc.y);
    atomicAdd(outp + 2, acc.z);
    atomicAdd(outp + 3, acc.w);
#pragma unroll
    for (int t = 0; t < 4; t++) {
        int j = lane + 32 * t;
        float anh = __shfl_sync(0xffffffffu, an, j >> 4);
        atomicAdd(&d_B[dst * 128 + j], anh * my_ea);
    }
}

// ---------------- node reduce: relu(vout + eterm + skip) -> pooled ----------------
__global__ __launch_bounds__(128) void node_reduce() {
    int c = threadIdx.x;
    int n0 = blockIdx.x * 64;
    int n1 = n0 + 64;
    if (n1 > N_NODES) n1 = N_NODES;
    float acc = 0.f;
    for (int n = n0; n < n1; n++) {
        float vv = d_vout[n * 128 + c] + d_eterm[n * 128 + c] + d_skip[n * 128 + c];
        acc += fmaxf(vv, 0.f);
    }
    atomicAdd(&d_pooled[c], acc);
}

// ---------------- final dot: pooled @ Wd + bd ----------------
__global__ __launch_bounds__(128) void final_dot(const float* __restrict__ Wd,
                                                 const float* __restrict__ bd,
                                                 float* __restrict__ out) {
    int t = threadIdx.x;
    float v = d_pooled[t] * Wd[t];
#pragma unroll
    for (int o = 16; o; o >>= 1) v += __shfl_xor_sync(0xffffffffu, v, o);
    __shared__ float red[4];
    if ((t & 31) == 0) red[t >> 5] = v;
    __syncthreads();
    if (t == 0) out[0] = red[0] + red[1] + red[2] + red[3] + bd[0];
}

extern "C" void kernel_launch(void* const* d_in, const int* in_sizes, int n_in,
                              void* d_out, int out_size) {
    const float* x         = (const float*)d_in[0];
    const float* edge_attr = (const float*)d_in[1];
    const int*   edge_index= (const int*)d_in[2];
    const float* Wq = (const float*)d_in[3];
    const float* bq = (const float*)d_in[4];
    const float* Wk = (const float*)d_in[5];
    const float* bk = (const float*)d_in[6];
    const float* Wv = (const float*)d_in[7];
    const float* bv = (const float*)d_in[8];
    const float* We = (const float*)d_in[9];
    const float* Wskip = (const float*)d_in[10];
    const float* bskip = (const float*)d_in[11];
    const float* Wd = (const float*)d_in[12];
    const float* bd = (const float*)d_in[13];
    float* out = (float*)d_out;

    init_kernel<<<5000, 256>>>();

    dim3 gqkv(HC / 128, (N_NODES + 127) / 128);   // (8, 79)
    dim3 g128(1, (N_NODES + 127) / 128);          // (1, 79)
    gemm_bias_kernel<<<gqkv, 256>>>(x, Wq, bq, 0, 0, N_NODES, HC);
    gemm_bias_kernel<<<gqkv, 256>>>(x, Wk, bk, 1, 0, N_NODES, HC);
    gemm_bias_kernel<<<gqkv, 256>>>(x, Wv, bv, 2, 0, N_NODES, HC);
    gemm_bias_kernel<<<g128, 256>>>(x, Wskip, bskip, 3, 0, N_NODES, OUT_CH);

    build_wer<<<64, 256>>>(We);
    g_kernel<<<592, 128>>>(We, 0);
    g_kernel<<<592, 128>>>(We, 64);

    dim3 eblk(32, 8);
    int egrid = (N_EDGES + 7) / 8;
    edge_alpha<<<egrid, eblk>>>(edge_attr, edge_index);
    edge_msg<<<egrid, eblk>>>(edge_attr, edge_index);

    gemm_bias_kernel<<<g128, 256>>>(nullptr, nullptr, nullptr, 4, 1, N_NODES, 128);

    node_reduce<<<(N_NODES + 63) / 64, 128>>>();
    final_dot<<<1, 128>>>(Wd, bd, out);
}

// round 2
// speedup vs baseline: 1.4444x; 1.4444x over previous
#include <cuda_runtime.h>
#include <cuda_bf16.h>
#include <stdint.h>
#include <math.h>

#define N_NODES 10000
#define N_EDGES 100000
#define F_NODE 128
#define F_EDGE 16
#define HEADS 8
#define OUT_CH 128
#define HC 1024  // HEADS*OUT_CH

// ---------------- scratch (device globals; no runtime allocation) ----------------
__device__ float d_q[N_NODES * HC];
__device__ float d_k[N_NODES * HC];
__device__ float d_v[N_NODES * HC];
__device__ float d_skip[N_NODES * OUT_CH];
__device__ float d_g[N_NODES * 128];       // g[n, h*16+f]
__device__ float d_aexp[N_EDGES * HEADS];  // exp(alpha)
__device__ float d_s[N_NODES * HEADS];     // softmax denominators
__device__ float d_vout[N_NODES * OUT_CH]; // v-term accumulation (head-mean folded)
__device__ float d_B[N_NODES * 128];       // B[n, h*16+f] = sum_e alpha_n*ea
__device__ float d_Wer[128 * 128];         // Wer[h*16+f][c] = We[f, h*128+c]
__device__ float d_Wg[1024 * 128];         // block-diag expansion of Wer^T for g GEMM
__device__ float d_pooled[OUT_CH];

// ---------------- init ----------------
__global__ void init_kernel() {
    int i = blockIdx.x * 256 + threadIdx.x;
    if (i < N_NODES * 128) { d_vout[i] = 0.f; d_B[i] = 0.f; }
    if (i < N_NODES * HEADS) d_s[i] = 0.f;
    if (i < OUT_CH) d_pooled[i] = 0.f;
}

// ---------------- small weight-prep kernels ----------------
__global__ void build_wer(const float* __restrict__ We) {
    int idx = blockIdx.x * 256 + threadIdx.x;
    if (idx < 128 * 128) {
        int j = idx >> 7, c = idx & 127;
        int h = j >> 4, f = j & 15;
        d_Wer[idx] = We[f * HC + h * 128 + c];
    }
}

// Wg[k=h'*128+c][j=h*16+f] = (h'==h) ? We[f, h*128+c] : 0
__global__ void build_wg(const float* __restrict__ We) {
    int idx = blockIdx.x * 256 + threadIdx.x;
    if (idx < 1024 * 128) {
        int k = idx >> 7, j = idx & 127;
        int h = j >> 4, f = j & 15;
        int c = k & 127, hk = k >> 7;
        d_Wg[idx] = (hk == h) ? We[f * HC + h * 128 + c] : 0.f;
    }
}

// ---------------- tensor-core GEMM (bf16 3-pass split, fp32 accurate) ----------------
// C[M,N] = A[M,K] @ W[K,N] (+bias). BM=128, BN=64, BK=32, 256 threads (8 warps, 4x2).
// asel: 0=param 1=d_B 2=d_q.  wsel: 0=param 1=d_Wg 2=d_Wer.
// out_sel: 0 q, 1 k, 2 v, 3 skip, 4 (fused reduce, no store), 5 g.
__device__ __forceinline__ void ldsm4(uint32_t* r, unsigned addr) {
    asm volatile("ldmatrix.sync.aligned.m8n8.x4.shared.b16 {%0,%1,%2,%3}, [%4];\n"
                 : "=r"(r[0]), "=r"(r[1]), "=r"(r[2]), "=r"(r[3]) : "r"(addr));
}
__device__ __forceinline__ void ldsm4t(uint32_t* r, unsigned addr) {
    asm volatile("ldmatrix.sync.aligned.m8n8.x4.trans.shared.b16 {%0,%1,%2,%3}, [%4];\n"
                 : "=r"(r[0]), "=r"(r[1]), "=r"(r[2]), "=r"(r[3]) : "r"(addr));
}
__device__ __forceinline__ void mma_bf16(float* c, uint32_t a0, uint32_t a1, uint32_t a2,
                                         uint32_t a3, uint32_t b0, uint32_t b1) {
    asm volatile(
        "mma.sync.aligned.m16n8k16.row.col.f32.bf16.bf16.f32 "
        "{%0,%1,%2,%3}, {%4,%5,%6,%7}, {%8,%9}, {%0,%1,%2,%3};\n"
        : "+f"(c[0]), "+f"(c[1]), "+f"(c[2]), "+f"(c[3])
        : "r"(a0), "r"(a1), "r"(a2), "r"(a3), "r"(b0), "r"(b1));
}

__global__ __launch_bounds__(256) void gemm_tc(
    const float* __restrict__ Ap, const float* __restrict__ Wp,
    const float* __restrict__ bias, int asel, int wsel, int out_sel,
    int M, int N, int K, int fuse) {
    const float* A = (asel == 1) ? d_B : (asel == 2) ? d_q : Ap;
    const float* W = (wsel == 1) ? d_Wg : (wsel == 2) ? d_Wer : Wp;
    float* C = (out_sel == 0) ? d_q : (out_sel == 1) ? d_k : (out_sel == 2) ? d_v
             : (out_sel == 3) ? d_skip : d_g;

    __shared__ __align__(16) __nv_bfloat16 sAh[128][40];
    __shared__ __align__(16) __nv_bfloat16 sAl[128][40];
    __shared__ __align__(16) __nv_bfloat16 sBh[32][72];
    __shared__ __align__(16) __nv_bfloat16 sBl[32][72];
    __shared__ float spool[64];

    int tid = threadIdx.x, w = tid >> 5, l = tid & 31;
    int bm = blockIdx.y * 128, bn = blockIdx.x * 64;
    int wm = (w >> 1) * 32, wn = (w & 1) * 32;
    if (fuse && tid < 64) spool[tid] = 0.f;

    float acc[2][4][4];
#pragma unroll
    for (int a = 0; a < 2; a++)
#pragma unroll
        for (int b = 0; b < 4; b++)
#pragma unroll
            for (int c = 0; c < 4; c++) acc[a][b][c] = 0.f;

    int a_r = (l & 7) + ((l >> 3) & 1) * 8;   // A ldmatrix row within 16
    int a_ko = ((l >> 4) & 1) * 8;            // A ldmatrix k offset
    int b_k = (l & 7) + ((l >> 3) & 1) * 8;   // B ldmatrix k-row within 16
    int b_no = ((l >> 4) & 1) * 8;            // B ldmatrix n offset

    for (int kc = 0; kc < K; kc += 32) {
        // load + split A tile [128 x 32]
#pragma unroll
        for (int i = 0; i < 4; i++) {
            int idx = tid + 256 * i;
            int row = idx >> 3, kq = (idx & 7) * 4;
            float4 av = make_float4(0.f, 0.f, 0.f, 0.f);
            int gr = bm + row;
            if (gr < M) av = *(const float4*)&A[(size_t)gr * K + kc + kq];
            float vs[4] = {av.x, av.y, av.z, av.w};
#pragma unroll
            for (int j = 0; j < 4; j++) {
                __nv_bfloat16 h = __float2bfloat16(vs[j]);
                sAh[row][kq + j] = h;
                sAl[row][kq + j] = __float2bfloat16(vs[j] - __bfloat162float(h));
            }
        }
        // load + split B tile [32 x 64]
#pragma unroll
        for (int i = 0; i < 2; i++) {
            int idx = tid + 256 * i;
            int k = idx >> 4, nq = (idx & 15) * 4;
            float4 wv = *(const float4*)&W[(size_t)(kc + k) * N + bn + nq];
            float vs[4] = {wv.x, wv.y, wv.z, wv.w};
#pragma unroll
            for (int j = 0; j < 4; j++) {
                __nv_bfloat16 h = __float2bfloat16(vs[j]);
                sBh[k][nq + j] = h;
                sBl[k][nq + j] = __float2bfloat16(vs[j] - __bfloat162float(h));
            }
        }
        __syncthreads();
#pragma unroll
        for (int k16 = 0; k16 < 2; k16++) {
            uint32_t Ah[2][4], Alo[2][4], Bh[2][4], Blo[2][4];
#pragma unroll
            for (int mt = 0; mt < 2; mt++) {
                ldsm4(Ah[mt], (unsigned)__cvta_generic_to_shared(
                                  &sAh[wm + mt * 16 + a_r][k16 * 16 + a_ko]));
                ldsm4(Alo[mt], (unsigned)__cvta_generic_to_shared(
                                   &sAl[wm + mt * 16 + a_r][k16 * 16 + a_ko]));
            }
#pragma unroll
            for (int p = 0; p < 2; p++) {
                ldsm4t(Bh[p], (unsigned)__cvta_generic_to_shared(
                                  &sBh[k16 * 16 + b_k][wn + p * 16 + b_no]));
                ldsm4t(Blo[p], (unsigned)__cvta_generic_to_shared(
                                   &sBl[k16 * 16 + b_k][wn + p * 16 + b_no]));
            }
            auto pass = [&](uint32_t(&Af)[2][4], uint32_t(&Bf)[2][4]) {
#pragma unroll
                for (int nt = 0; nt < 4; nt++) {
                    uint32_t b0 = Bf[nt >> 1][(nt & 1) * 2];
                    uint32_t b1 = Bf[nt >> 1][(nt & 1) * 2 + 1];
#pragma unroll
                    for (int mt = 0; mt < 2; mt++)
                        mma_bf16(acc[mt][nt], Af[mt][0], Af[mt][1], Af[mt][2], Af[mt][3],
                                 b0, b1);
                }
            };
            pass(Ah, Bh);
            pass(Ah, Blo);
            pass(Alo, Bh);
        }
        __syncthreads();
    }

    int r0 = l >> 2, cql = (l & 3) * 2;
    if (!fuse) {
#pragma unroll
        for (int mt = 0; mt < 2; mt++) {
            int row = bm + wm + mt * 16 + r0;
#pragma unroll
            for (int nt = 0; nt < 4; nt++) {
                int col = bn + wn + nt * 8 + cql;
                float b0v = bias ? bias[col] : 0.f;
                float b1v = bias ? bias[col + 1] : 0.f;
                if (row < M) {
                    C[(size_t)row * N + col] = acc[mt][nt][0] + b0v;
                    C[(size_t)row * N + col + 1] = acc[mt][nt][1] + b1v;
                }
                if (row + 8 < M) {
                    C[(size_t)(row + 8) * N + col] = acc[mt][nt][2] + b0v;
                    C[(size_t)(row + 8) * N + col + 1] = acc[mt][nt][3] + b1v;
                }
            }
        }
    } else {
        // eterm fused: relu(eterm + vout + skip) column-summed into d_pooled
#pragma unroll
        for (int nt = 0; nt < 4; nt++) {
            int col = bn + wn + nt * 8 + cql;
            float s0 = 0.f, s1 = 0.f;
#pragma unroll
            for (int mt = 0; mt < 2; mt++) {
                int row = bm + wm + mt * 16 + r0;
                if (row < M) {
                    s0 += fmaxf(acc[mt][nt][0] + d_vout[row * 128 + col] +
                                    d_skip[row * 128 + col], 0.f);
                    s1 += fmaxf(acc[mt][nt][1] + d_vout[row * 128 + col + 1] +
                                    d_skip[row * 128 + col + 1], 0.f);
                }
                if (row + 8 < M) {
                    s0 += fmaxf(acc[mt][nt][2] + d_vout[(row + 8) * 128 + col] +
                                    d_skip[(row + 8) * 128 + col], 0.f);
                    s1 += fmaxf(acc[mt][nt][3] + d_vout[(row + 8) * 128 + col + 1] +
                                    d_skip[(row + 8) * 128 + col + 1], 0.f);
                }
            }
#pragma unroll
            for (int off = 16; off >= 4; off >>= 1) {
                s0 += __shfl_xor_sync(0xffffffffu, s0, off);
                s1 += __shfl_xor_sync(0xffffffffu, s1, off);
            }
            if (l < 4) {
                atomicAdd(&spool[wn + nt * 8 + cql], s0);
                atomicAdd(&spool[wn + nt * 8 + cql + 1], s1);
            }
        }
        __syncthreads();
        if (tid < 64) atomicAdd(&d_pooled[bn + tid], spool[tid]);
    }
}

// ---------------- edge pass A: alpha -> exp -> atomic sum ----------------
__global__ __launch_bounds__(256) void edge_alpha(const float* __restrict__ ea,
                                                  const int* __restrict__ eidx) {
    int e = blockIdx.x * 8 + threadIdx.y;
    if (e >= N_EDGES) return;
    int lane = threadIdx.x;
    int src = eidx[e];
    int dst = eidx[N_EDGES + e];
    const float4* q4 = (const float4*)&d_q[dst * HC];
    const float4* k4 = (const float4*)&d_k[src * HC];
    float myalpha = 0.f;
#pragma unroll
    for (int h = 0; h < 8; h++) {
        float4 a = q4[h * 32 + lane];
        float4 b = k4[h * 32 + lane];
        float dp = a.x * b.x + a.y * b.y + a.z * b.z + a.w * b.w;
#pragma unroll
        for (int o = 16; o; o >>= 1) dp += __shfl_xor_sync(0xffffffffu, dp, o);
        if (lane == h) myalpha = dp;
    }
    if (lane < 8) {
        float et = 0.f;
        const float* gp = &d_g[dst * 128 + lane * 16];
        const float* eap = &ea[e * F_EDGE];
#pragma unroll
        for (int f = 0; f < 16; f++) et += eap[f] * gp[f];
        float alpha = (myalpha + et) * 0.08838834764831845f;  // 1/sqrt(128)
        float aex = expf(alpha);
        d_aexp[e * 8 + lane] = aex;
        atomicAdd(&d_s[dst * 8 + lane], aex);
    }
}

// ---------------- edge pass B: v-term scatter + B-coefficient scatter ----------------
__global__ __launch_bounds__(256) void edge_msg(const float* __restrict__ ea,
                                                const int* __restrict__ eidx) {
    int e = blockIdx.x * 8 + threadIdx.y;
    if (e >= N_EDGES) return;
    int lane = threadIdx.x;
    int src = eidx[e];
    int dst = eidx[N_EDGES + e];
    float an = 0.f;
    if (lane < 8) {
        float s = d_s[dst * 8 + lane];
        an = 0.125f * d_aexp[e * 8 + lane] / (s + 1e-16f);  // head-mean folded
    }
    float eaf = 0.f;
    if (lane < 16) eaf = ea[e * F_EDGE + lane];
    float my_ea = __shfl_sync(0xffffffffu, eaf, lane & 15);

    const float4* v4 = (const float4*)&d_v[src * HC];
    float4 acc = make_float4(0.f, 0.f, 0.f, 0.f);
#pragma unroll
    for (int h = 0; h < 8; h++) {
        float anh = __shfl_sync(0xffffffffu, an, h);
        float4 vv = v4[h * 32 + lane];
        acc.x += anh * vv.x;
        acc.y += anh * vv.y;
        acc.z += anh * vv.z;
        acc.w += anh * vv.w;
    }
    float* outp = &d_vout[dst * 128 + lane * 4];
    atomicAdd(outp + 0, acc.x);
    atomicAdd(outp + 1, acc.y);
    atomicAdd(outp + 2, acc.z);
    atomicAdd(outp + 3, acc.w);
#pragma unroll
    for (int t = 0; t < 4; t++) {
        int j = lane + 32 * t;
        float anh = __shfl_sync(0xffffffffu, an, j >> 4);
        atomicAdd(&d_B[dst * 128 + j], anh * my_ea);
    }
}

// ---------------- final dot: pooled @ Wd + bd ----------------
__global__ __launch_bounds__(128) void final_dot(const float* __restrict__ Wd,
                                                 const float* __restrict__ bd,
                                                 float* __restrict__ out) {
    int t = threadIdx.x;
    float v = d_pooled[t] * Wd[t];
#pragma unroll
    for (int o = 16; o; o >>= 1) v += __shfl_xor_sync(0xffffffffu, v, o);
    __shared__ float red[4];
    if ((t & 31) == 0) red[t >> 5] = v;
    __syncthreads();
    if (t == 0) out[0] = red[0] + red[1] + red[2] + red[3] + bd[0];
}

extern "C" void kernel_launch(void* const* d_in, const int* in_sizes, int n_in,
                              void* d_out, int out_size) {
    const float* x          = (const float*)d_in[0];
    const float* edge_attr  = (const float*)d_in[1];
    const int*   edge_index = (const int*)d_in[2];
    const float* Wq = (const float*)d_in[3];
    const float* bq = (const float*)d_in[4];
    const float* Wk = (const float*)d_in[5];
    const float* bk = (const float*)d_in[6];
    const float* Wv = (const float*)d_in[7];
    const float* bv = (const float*)d_in[8];
    const float* We = (const float*)d_in[9];
    const float* Wskip = (const float*)d_in[10];
    const float* bskip = (const float*)d_in[11];
    const float* Wd = (const float*)d_in[12];
    const float* bd = (const float*)d_in[13];
    float* out = (float*)d_out;

    init_kernel<<<5000, 256>>>();

    // q, k, v: [10000,128] @ [128,1024]
    gemm_tc<<<dim3(16, 79), 256>>>(x, Wq, bq, 0, 0, 0, N_NODES, HC, F_NODE, 0);
    gemm_tc<<<dim3(16, 79), 256>>>(x, Wk, bk, 0, 0, 1, N_NODES, HC, F_NODE, 0);
    gemm_tc<<<dim3(16, 79), 256>>>(x, Wv, bv, 0, 0, 2, N_NODES, HC, F_NODE, 0);
    // skip: [10000,128] @ [128,128]
    gemm_tc<<<dim3(2, 79), 256>>>(x, Wskip, bskip, 0, 0, 3, N_NODES, 128, F_NODE, 0);

    build_wer<<<64, 256>>>(We);
    build_wg<<<512, 256>>>(We);
    // g = q @ Wg : [10000,1024] @ [1024,128]
    gemm_tc<<<dim3(2, 79), 256>>>(nullptr, nullptr, nullptr, 2, 1, 5, N_NODES, 128, HC, 0);

    dim3 eblk(32, 8);
    int egrid = (N_EDGES + 7) / 8;
    edge_alpha<<<egrid, eblk>>>(edge_attr, edge_index);
    edge_msg<<<egrid, eblk>>>(edge_attr, edge_index);

    // eterm = B @ Wer with fused relu(eterm+vout+skip) column-sum into pooled
    gemm_tc<<<dim3(2, 79), 256>>>(nullptr, nullptr, nullptr, 1, 2, 4, N_NODES, 128, 128, 1);

    final_dot<<<1, 128>>>(Wd, bd, out);
}

// round 3
// speedup vs baseline: 2.0377x; 1.4107x over previous
#include <cuda_runtime.h>
#include <cuda_bf16.h>
#include <stdint.h>
#include <math.h>

#define N_NODES 10000
#define N_EDGES 100000
#define F_NODE 128
#define F_EDGE 16
#define HEADS 8
#define OUT_CH 128
#define HC 1024
#define NQKVS 3200   // 3*1024 + 128 fused output columns

// ---------------- scratch (device globals) ----------------
__device__ __nv_bfloat16 d_xh[N_NODES * 128];
__device__ __nv_bfloat16 d_xl[N_NODES * 128];
__device__ __nv_bfloat16 d_qb[N_NODES * HC];
__device__ __nv_bfloat16 d_kb[N_NODES * HC];
__device__ __nv_bfloat16 d_vb[N_NODES * HC];
__device__ __nv_bfloat16 d_Bb[N_NODES * 128];
__device__ __nv_bfloat16 d_Wqh[128 * NQKVS];
__device__ __nv_bfloat16 d_Wql[128 * NQKVS];
__device__ __nv_bfloat16 d_Wgh[1024 * 128];
__device__ __nv_bfloat16 d_Wgl[1024 * 128];
__device__ __nv_bfloat16 d_Werh[128 * 128];
__device__ __nv_bfloat16 d_Werl[128 * 128];
__device__ float d_biasc[NQKVS];
__device__ float d_skip[N_NODES * 128];
__device__ float d_g[N_NODES * 128];
__device__ float d_aexp[N_EDGES * HEADS];
__device__ float d_s[N_NODES * HEADS];
__device__ float d_vout[N_NODES * 128];
__device__ float d_B[N_NODES * 128];
__device__ float d_pooled[128];

// ---------------- init ----------------
__global__ void init_kernel() {
    int i = blockIdx.x * 256 + threadIdx.x;
    if (i < N_NODES * 128) { d_vout[i] = 0.f; d_B[i] = 0.f; }
    if (i < N_NODES * HEADS) d_s[i] = 0.f;
    if (i < 128) d_pooled[i] = 0.f;
}

// ---------------- prep kernels ----------------
__global__ void split_x(const float* __restrict__ x) {
    int i = blockIdx.x * 256 + threadIdx.x;
    if (i < N_NODES * 128) {
        float v = x[i];
        __nv_bfloat16 h = __float2bfloat16(v);
        d_xh[i] = h;
        d_xl[i] = __float2bfloat16(v - __bfloat162float(h));
    }
}

__global__ void pack_w(const float* __restrict__ Wq, const float* __restrict__ Wk,
                       const float* __restrict__ Wv, const float* __restrict__ Ws,
                       const float* __restrict__ bq, const float* __restrict__ bk,
                       const float* __restrict__ bv, const float* __restrict__ bs) {
    int idx = blockIdx.x * 256 + threadIdx.x;
    if (idx < 128 * NQKVS) {
        int k = idx / NQKVS, col = idx % NQKVS;
        float v;
        if (col < 1024) v = Wq[k * HC + col];
        else if (col < 2048) v = Wk[k * HC + col - 1024];
        else if (col < 3072) v = Wv[k * HC + col - 2048];
        else v = Ws[k * 128 + col - 3072];
        __nv_bfloat16 h = __float2bfloat16(v);
        d_Wqh[idx] = h;
        d_Wql[idx] = __float2bfloat16(v - __bfloat162float(h));
    }
    if (idx < NQKVS) {
        float b;
        if (idx < 1024) b = bq[idx];
        else if (idx < 2048) b = bk[idx - 1024];
        else if (idx < 3072) b = bv[idx - 2048];
        else b = bs[idx - 3072];
        d_biasc[idx] = b;
    }
}

// Wg[k=h'*128+c][j=h*16+f] = (h'==h)? We[f, h*128+c] : 0
__global__ void build_wg(const float* __restrict__ We) {
    int idx = blockIdx.x * 256 + threadIdx.x;
    if (idx < 1024 * 128) {
        int k = idx >> 7, j = idx & 127;
        int h = j >> 4, f = j & 15;
        int c = k & 127, hk = k >> 7;
        float v = (hk == h) ? We[f * HC + h * 128 + c] : 0.f;
        __nv_bfloat16 hh = __float2bfloat16(v);
        d_Wgh[idx] = hh;
        d_Wgl[idx] = __float2bfloat16(v - __bfloat162float(hh));
    }
}

__global__ void build_wer(const float* __restrict__ We) {
    int idx = blockIdx.x * 256 + threadIdx.x;
    if (idx < 128 * 128) {
        int j = idx >> 7, c = idx & 127;
        int h = j >> 4, f = j & 15;
        float v = We[f * HC + h * 128 + c];
        __nv_bfloat16 hh = __float2bfloat16(v);
        d_Werh[idx] = hh;
        d_Werl[idx] = __float2bfloat16(v - __bfloat162float(hh));
    }
}

__global__ void split_B() {
    int i = blockIdx.x * 256 + threadIdx.x;
    if (i < N_NODES * 128) d_Bb[i] = __float2bfloat16(d_B[i]);
}

// ---------------- MMA helpers ----------------
__device__ __forceinline__ void ldsm4(uint32_t* r, const void* p) {
    unsigned a = (unsigned)__cvta_generic_to_shared(p);
    asm volatile("ldmatrix.sync.aligned.m8n8.x4.shared.b16 {%0,%1,%2,%3}, [%4];\n"
                 : "=r"(r[0]), "=r"(r[1]), "=r"(r[2]), "=r"(r[3]) : "r"(a));
}
__device__ __forceinline__ void ldsm4t(uint32_t* r, const void* p) {
    unsigned a = (unsigned)__cvta_generic_to_shared(p);
    asm volatile("ldmatrix.sync.aligned.m8n8.x4.trans.shared.b16 {%0,%1,%2,%3}, [%4];\n"
                 : "=r"(r[0]), "=r"(r[1]), "=r"(r[2]), "=r"(r[3]) : "r"(a));
}
__device__ __forceinline__ void mma_bf16(float* c, const uint32_t* a, uint32_t b0,
                                         uint32_t b1) {
    asm volatile(
        "mma.sync.aligned.m16n8k16.row.col.f32.bf16.bf16.f32 "
        "{%0,%1,%2,%3}, {%4,%5,%6,%7}, {%8,%9}, {%0,%1,%2,%3};\n"
        : "+f"(c[0]), "+f"(c[1]), "+f"(c[2]), "+f"(c[3])
        : "r"(a[0]), "r"(a[1]), "r"(a[2]), "r"(a[3]), "r"(b0), "r"(b1));
}
__device__ __forceinline__ void cp16(void* sdst, const void* gsrc, bool pred) {
    unsigned s = (unsigned)__cvta_generic_to_shared(sdst);
    int sz = pred ? 16 : 0;
    asm volatile("cp.async.cg.shared.global [%0], [%1], 16, %2;\n" ::"r"(s), "l"(gsrc),
                 "r"(sz));
}

// ---------------- unified TC GEMM, double-buffered, pre-split bf16 ----------------
// asel: 0 = (d_xh,d_xl) 3-pass; 1 = d_qb 2-pass; 2 = d_Bb 2-pass.
// wsel: 0 = Wqkvs pack; 1 = Wg (block-diag, k-range derived from bn); 2 = Wer.
// osel: 0 = qkv(bf16)+skip(f32); 1 = g f32; 2 = eterm fused reduce.
__global__ __launch_bounds__(256) void gemm_tc(int asel, int wsel, int osel, int M,
                                               int N, int Kstride, int kcount) {
    const __nv_bfloat16 *Ah, *Al = nullptr, *Wh, *Wl;
    if (asel == 0) { Ah = d_xh; Al = d_xl; }
    else if (asel == 1) Ah = d_qb;
    else Ah = d_Bb;
    if (wsel == 0) { Wh = d_Wqh; Wl = d_Wql; }
    else if (wsel == 1) { Wh = d_Wgh; Wl = d_Wgl; }
    else { Wh = d_Werh; Wl = d_Werl; }
    const bool has_al = (asel == 0);

    extern __shared__ __align__(16) char dyn[];
    __nv_bfloat16* dynb = (__nv_bfloat16*)dyn;
    float* spool = (float*)(dyn + 59392);

    int tid = threadIdx.x, w = tid >> 5, l = tid & 31;
    int bm = blockIdx.y * 128, bn = blockIdx.x * 64;
    int wm = (w >> 1) * 32, wn = (w & 1) * 32;
    int kbeg = (wsel == 1) ? blockIdx.x * 512 : 0;
    if (osel == 2 && tid < 64) spool[tid] = 0.f;

    float acc[2][4][4];
#pragma unroll
    for (int a = 0; a < 2; a++)
#pragma unroll
        for (int b = 0; b < 4; b++)
#pragma unroll
            for (int c = 0; c < 4; c++) acc[a][b][c] = 0.f;

    int a_r = (l & 7) + ((l >> 3) & 1) * 8;
    int a_ko = ((l >> 4) & 1) * 8;

    auto pA = [&](int st, int p) { return dynb + (st * 2 + p) * 5120; };
    auto pW = [&](int st, int p) { return dynb + 20480 + (st * 2 + p) * 2304; };

    auto load_stage = [&](int st, int kc) {
        int nh = has_al ? 2 : 1;
        for (int p = 0; p < nh; p++) {
            const __nv_bfloat16* As = p ? Al : Ah;
            __nv_bfloat16* dst = pA(st, p);
#pragma unroll
            for (int i = 0; i < 2; i++) {
                int idx = tid + 256 * i;
                int row = idx >> 2, ch = idx & 3;
                int gr = bm + row;
                cp16(dst + row * 40 + ch * 8, As + (size_t)gr * Kstride + kc + ch * 8,
                     gr < M);
            }
        }
        for (int p = 0; p < 2; p++) {
            const __nv_bfloat16* Ws = p ? Wl : Wh;
            __nv_bfloat16* dst = pW(st, p);
            int k = tid >> 3, ch = tid & 7;
            cp16(dst + k * 72 + ch * 8, Ws + (size_t)(kc + k) * N + bn + ch * 8, true);
        }
        asm volatile("cp.async.commit_group;\n" ::);
    };

    auto compute = [&](int st) {
#pragma unroll
        for (int k16 = 0; k16 < 2; k16++) {
            uint32_t Af[2][4], Alf[2][4], Bhf[2][4], Blf[2][4];
            __nv_bfloat16* ah = pA(st, 0);
#pragma unroll
            for (int mt = 0; mt < 2; mt++)
                ldsm4(Af[mt], ah + (wm + mt * 16 + a_r) * 40 + k16 * 16 + a_ko);
            __nv_bfloat16* wh = pW(st, 0);
            __nv_bfloat16* wl = pW(st, 1);
#pragma unroll
            for (int p = 0; p < 2; p++) {
                ldsm4t(Bhf[p], wh + (k16 * 16 + a_r) * 72 + wn + p * 16 + a_ko);
                ldsm4t(Blf[p], wl + (k16 * 16 + a_r) * 72 + wn + p * 16 + a_ko);
            }
            if (has_al) {
                __nv_bfloat16* al = pA(st, 1);
#pragma unroll
                for (int mt = 0; mt < 2; mt++)
                    ldsm4(Alf[mt], al + (wm + mt * 16 + a_r) * 40 + k16 * 16 + a_ko);
            }
#pragma unroll
            for (int nt = 0; nt < 4; nt++) {
                uint32_t bh0 = Bhf[nt >> 1][(nt & 1) * 2], bh1 = Bhf[nt >> 1][(nt & 1) * 2 + 1];
                uint32_t bl0 = Blf[nt >> 1][(nt & 1) * 2], bl1 = Blf[nt >> 1][(nt & 1) * 2 + 1];
#pragma unroll
                for (int mt = 0; mt < 2; mt++) {
                    mma_bf16(acc[mt][nt], Af[mt], bh0, bh1);
                    mma_bf16(acc[mt][nt], Af[mt], bl0, bl1);
                    if (has_al) mma_bf16(acc[mt][nt], Alf[mt], bh0, bh1);
                }
            }
        }
    };

    int nIter = kcount >> 5;
    load_stage(0, kbeg);
    for (int it = 0; it < nIter; it++) {
        if (it + 1 < nIter) {
            load_stage((it + 1) & 1, kbeg + (it + 1) * 32);
            asm volatile("cp.async.wait_group 1;\n" ::);
        } else {
            asm volatile("cp.async.wait_group 0;\n" ::);
        }
        __syncthreads();
        compute(it & 1);
        __syncthreads();
    }

    int r0 = l >> 2, cq = (l & 3) * 2;
    if (osel == 0) {
        auto st1 = [&](int row, int col, float v) {
            if (col < 1024) d_qb[row * HC + col] = __float2bfloat16(v);
            else if (col < 2048) d_kb[row * HC + col - 1024] = __float2bfloat16(v);
            else if (col < 3072) d_vb[row * HC + col - 2048] = __float2bfloat16(v);
            else d_skip[row * 128 + col - 3072] = v;
        };
#pragma unroll
        for (int mt = 0; mt < 2; mt++)
#pragma unroll
            for (int nt = 0; nt < 4; nt++) {
                int col = bn + wn + nt * 8 + cq;
                float bb0 = d_biasc[col], bb1 = d_biasc[col + 1];
#pragma unroll
                for (int rr = 0; rr < 2; rr++) {
                    int row = bm + wm + mt * 16 + r0 + rr * 8;
                    if (row < M) {
                        st1(row, col, acc[mt][nt][rr * 2] + bb0);
                        st1(row, col + 1, acc[mt][nt][rr * 2 + 1] + bb1);
                    }
                }
            }
    } else if (osel == 1) {
#pragma unroll
        for (int mt = 0; mt < 2; mt++)
#pragma unroll
            for (int nt = 0; nt < 4; nt++) {
                int col = bn + wn + nt * 8 + cq;
#pragma unroll
                for (int rr = 0; rr < 2; rr++) {
                    int row = bm + wm + mt * 16 + r0 + rr * 8;
                    if (row < M) {
                        d_g[row * 128 + col] = acc[mt][nt][rr * 2];
                        d_g[row * 128 + col + 1] = acc[mt][nt][rr * 2 + 1];
                    }
                }
            }
    } else {
#pragma unroll
        for (int nt = 0; nt < 4; nt++) {
            int col = bn + wn + nt * 8 + cq;
            float s0 = 0.f, s1 = 0.f;
#pragma unroll
            for (int mt = 0; mt < 2; mt++)
#pragma unroll
                for (int rr = 0; rr < 2; rr++) {
                    int row = bm + wm + mt * 16 + r0 + rr * 8;
                    if (row < M) {
                        s0 += fmaxf(acc[mt][nt][rr * 2] + d_vout[row * 128 + col] +
                                        d_skip[row * 128 + col], 0.f);
                        s1 += fmaxf(acc[mt][nt][rr * 2 + 1] + d_vout[row * 128 + col + 1] +
                                        d_skip[row * 128 + col + 1], 0.f);
                    }
                }
#pragma unroll
            for (int off = 16; off >= 4; off >>= 1) {
                s0 += __shfl_xor_sync(0xffffffffu, s0, off);
                s1 += __shfl_xor_sync(0xffffffffu, s1, off);
            }
            if (l < 4) {
                atomicAdd(&spool[wn + nt * 8 + cq], s0);
                atomicAdd(&spool[wn + nt * 8 + cq + 1], s1);
            }
        }
        __syncthreads();
        if (tid < 64) atomicAdd(&d_pooled[bn + tid], spool[tid]);
    }
}

// ---------------- edge pass A: alpha (bf16 gathers) ----------------
__global__ __launch_bounds__(256) void edge_alpha(const float* __restrict__ ea,
                                                  const int* __restrict__ eidx) {
    int e = blockIdx.x * 8 + threadIdx.y;
    if (e >= N_EDGES) return;
    int lane = threadIdx.x;
    int src = eidx[e];
    int dst = eidx[N_EDGES + e];
    const uint2* q2 = (const uint2*)&d_qb[dst * HC];
    const uint2* k2 = (const uint2*)&d_kb[src * HC];
    float myalpha = 0.f;
#pragma unroll
    for (int h = 0; h < 8; h++) {
        uint2 qa = q2[h * 32 + lane];
        uint2 kb = k2[h * 32 + lane];
        float2 q0 = __bfloat1622float2(*(__nv_bfloat162*)&qa.x);
        float2 q1 = __bfloat1622float2(*(__nv_bfloat162*)&qa.y);
        float2 k0 = __bfloat1622float2(*(__nv_bfloat162*)&kb.x);
        float2 k1 = __bfloat1622float2(*(__nv_bfloat162*)&kb.y);
        float dp = q0.x * k0.x + q0.y * k0.y + q1.x * k1.x + q1.y * k1.y;
#pragma unroll
        for (int o = 16; o; o >>= 1) dp += __shfl_xor_sync(0xffffffffu, dp, o);
        if (lane == h) myalpha = dp;
    }
    if (lane < 8) {
        float et = 0.f;
        const float* gp = &d_g[dst * 128 + lane * 16];
        const float* eap = &ea[e * F_EDGE];
#pragma unroll
        for (int f = 0; f < 16; f++) et += eap[f] * gp[f];
        float alpha = (myalpha + et) * 0.08838834764831845f;
        float aex = expf(alpha);
        d_aexp[e * 8 + lane] = aex;
        atomicAdd(&d_s[dst * 8 + lane], aex);
    }
}

// ---------------- edge pass B: v-term + B scatter (v4 reductions) ----------------
__global__ __launch_bounds__(256) void edge_msg(const float* __restrict__ ea,
                                                const int* __restrict__ eidx) {
    int e = blockIdx.x * 8 + threadIdx.y;
    if (e >= N_EDGES) return;
    int lane = threadIdx.x;
    int src = eidx[e];
    int dst = eidx[N_EDGES + e];
    float an = 0.f;
    if (lane < 8) {
        float s = d_s[dst * 8 + lane];
        an = 0.125f * d_aexp[e * 8 + lane] / (s + 1e-16f);
    }
    float4 ea4 = ((const float4*)&ea[e * F_EDGE])[lane & 3];

    const uint2* v2 = (const uint2*)&d_vb[src * HC];
    float4 acc = make_float4(0.f, 0.f, 0.f, 0.f);
#pragma unroll
    for (int h = 0; h < 8; h++) {
        float anh = __shfl_sync(0xffffffffu, an, h);
        uint2 vv = v2[h * 32 + lane];
        float2 v0 = __bfloat1622float2(*(__nv_bfloat162*)&vv.x);
        float2 v1 = __bfloat1622float2(*(__nv_bfloat162*)&vv.y);
        acc.x += anh * v0.x;
        acc.y += anh * v0.y;
        acc.z += anh * v1.x;
        acc.w += anh * v1.y;
    }
    float* outp = &d_vout[dst * 128 + lane * 4];
    asm volatile("red.global.add.v4.f32 [%0], {%1,%2,%3,%4};\n" ::"l"(outp), "f"(acc.x),
                 "f"(acc.y), "f"(acc.z), "f"(acc.w)
                 : "memory");

    float anj = __shfl_sync(0xffffffffu, an, lane >> 2);
    float* bp = &d_B[dst * 128 + lane * 4];
    asm volatile("red.global.add.v4.f32 [%0], {%1,%2,%3,%4};\n" ::"l"(bp),
                 "f"(anj * ea4.x), "f"(anj * ea4.y), "f"(anj * ea4.z), "f"(anj * ea4.w)
                 : "memory");
}

// ---------------- final dot ----------------
__global__ __launch_bounds__(128) void final_dot(const float* __restrict__ Wd,
                                                 const float* __restrict__ bd,
                                                 float* __restrict__ out) {
    int t = threadIdx.x;
    float v = d_pooled[t] * Wd[t];
#pragma unroll
    for (int o = 16; o; o >>= 1) v += __shfl_xor_sync(0xffffffffu, v, o);
    __shared__ float red[4];
    if ((t & 31) == 0) red[t >> 5] = v;
    __syncthreads();
    if (t == 0) out[0] = red[0] + red[1] + red[2] + red[3] + bd[0];
}

extern "C" void kernel_launch(void* const* d_in, const int* in_sizes, int n_in,
                              void* d_out, int out_size) {
    const float* x          = (const float*)d_in[0];
    const float* edge_attr  = (const float*)d_in[1];
    const int*   edge_index = (const int*)d_in[2];
    const float* Wq = (const float*)d_in[3];
    const float* bq = (const float*)d_in[4];
    const float* Wk = (const float*)d_in[5];
    const float* bk = (const float*)d_in[6];
    const float* Wv = (const float*)d_in[7];
    const float* bv = (const float*)d_in[8];
    const float* We = (const float*)d_in[9];
    const float* Wskip = (const float*)d_in[10];
    const float* bskip = (const float*)d_in[11];
    const float* Wd = (const float*)d_in[12];
    const float* bd = (const float*)d_in[13];
    float* out = (float*)d_out;

    static int attr_done = 0;
    if (!attr_done) {
        cudaFuncSetAttribute(gemm_tc, cudaFuncAttributeMaxDynamicSharedMemorySize, 60416);
        attr_done = 1;
    }

    init_kernel<<<5000, 256>>>();
    split_x<<<5000, 256>>>(x);
    pack_w<<<1600, 256>>>(Wq, Wk, Wv, Wskip, bq, bk, bv, bskip);
    build_wg<<<512, 256>>>(We);
    build_wer<<<64, 256>>>(We);

    // fused q|k|v|skip : [10000,128] @ [128,3200]
    gemm_tc<<<dim3(50, 79), 256, 59648>>>(0, 0, 0, N_NODES, NQKVS, 128, 128);
    // g = q @ Wg (block-diag: each n-block uses its 512-wide k-slice)
    gemm_tc<<<dim3(2, 79), 256, 59648>>>(1, 1, 1, N_NODES, 128, 1024, 512);

    dim3 eblk(32, 8);
    edge_alpha<<<12500, eblk>>>(edge_attr, edge_index);
    edge_msg<<<12500, eblk>>>(edge_attr, edge_index);

    split_B<<<5000, 256>>>();
    // eterm = B @ Wer, fused relu(eterm+vout+skip) column-sum into pooled
    gemm_tc<<<dim3(2, 79), 256, 59648>>>(2, 2, 2, N_NODES, 128, 128, 128);

    final_dot<<<1, 128>>>(Wd, bd, out);
}

// round 4
// speedup vs baseline: 2.2788x; 1.1183x over previous
#include <cuda_runtime.h>
#include <cuda_bf16.h>
#include <stdint.h>
#include <math.h>

#define N_NODES 10000
#define N_EDGES 100000
#define F_NODE 128
#define F_EDGE 16
#define HEADS 8
#define OUT_CH 128
#define HC 1024
#define NQKVS 3200   // 3*1024 + 128 fused output columns

// ---------------- scratch (device globals) ----------------
__device__ __nv_bfloat16 d_xh[N_NODES * 128];
__device__ __nv_bfloat16 d_xl[N_NODES * 128];
__device__ __nv_bfloat16 d_qb[N_NODES * HC];
__device__ __nv_bfloat16 d_kb[N_NODES * HC];
__device__ __nv_bfloat16 d_vb[N_NODES * HC];
__device__ __nv_bfloat16 d_Bb[N_NODES * 128];
__device__ __nv_bfloat16 d_Wqh[128 * NQKVS];
__device__ __nv_bfloat16 d_Wql[128 * NQKVS];
__device__ __nv_bfloat16 d_Wgh[1024 * 128];
__device__ __nv_bfloat16 d_Wgl[1024 * 128];
__device__ __nv_bfloat16 d_Werh[128 * 128];
__device__ __nv_bfloat16 d_Werl[128 * 128];
__device__ float d_biasc[NQKVS];
__device__ float d_skip[N_NODES * 128];
__device__ float d_g[N_NODES * 128];
__device__ float d_aexp[N_EDGES * HEADS];
__device__ float d_s[N_NODES * HEADS];
__device__ float d_vout[N_NODES * 128];
__device__ float d_B[N_NODES * 128];
__device__ float d_pooled[128];

// ---------------- fused prep: split_x | pack_w | bias | build_wg | build_wer ----
#define SEG0 (N_NODES * 128)                 // split_x
#define SEG1 (128 * NQKVS)                   // pack_w
#define SEG2 (NQKVS)                         // bias
#define SEG3 (1024 * 128)                    // build_wg
#define SEG4 (128 * 128)                     // build_wer
#define PREP_TOTAL (SEG0 + SEG1 + SEG2 + SEG3 + SEG4)

__global__ __launch_bounds__(256) void prep_all(
    const float* __restrict__ x, const float* __restrict__ Wq,
    const float* __restrict__ Wk, const float* __restrict__ Wv,
    const float* __restrict__ Ws, const float* __restrict__ bq,
    const float* __restrict__ bk, const float* __restrict__ bv,
    const float* __restrict__ bs, const float* __restrict__ We) {
    int idx = blockIdx.x * 256 + threadIdx.x;
    if (idx < SEG0) {
        float v = x[idx];
        __nv_bfloat16 h = __float2bfloat16(v);
        d_xh[idx] = h;
        d_xl[idx] = __float2bfloat16(v - __bfloat162float(h));
        return;
    }
    idx -= SEG0;
    if (idx < SEG1) {
        int k = idx / NQKVS, col = idx % NQKVS;
        float v;
        if (col < 1024) v = Wq[k * HC + col];
        else if (col < 2048) v = Wk[k * HC + col - 1024];
        else if (col < 3072) v = Wv[k * HC + col - 2048];
        else v = Ws[k * 128 + col - 3072];
        __nv_bfloat16 h = __float2bfloat16(v);
        d_Wqh[idx] = h;
        d_Wql[idx] = __float2bfloat16(v - __bfloat162float(h));
        return;
    }
    idx -= SEG1;
    if (idx < SEG2) {
        float b;
        if (idx < 1024) b = bq[idx];
        else if (idx < 2048) b = bk[idx - 1024];
        else if (idx < 3072) b = bv[idx - 2048];
        else b = bs[idx - 3072];
        d_biasc[idx] = b;
        return;
    }
    idx -= SEG2;
    if (idx < SEG3) {
        int k = idx >> 7, j = idx & 127;
        int h = j >> 4, f = j & 15;
        int c = k & 127, hk = k >> 7;
        float v = (hk == h) ? We[f * HC + h * 128 + c] : 0.f;
        __nv_bfloat16 hh = __float2bfloat16(v);
        d_Wgh[idx] = hh;
        d_Wgl[idx] = __float2bfloat16(v - __bfloat162float(hh));
        return;
    }
    idx -= SEG3;
    if (idx < SEG4) {
        int j = idx >> 7, c = idx & 127;
        int h = j >> 4, f = j & 15;
        float v = We[f * HC + h * 128 + c];
        __nv_bfloat16 hh = __float2bfloat16(v);
        d_Werh[idx] = hh;
        d_Werl[idx] = __float2bfloat16(v - __bfloat162float(hh));
    }
}

__global__ void split_B() {
    int i = blockIdx.x * 256 + threadIdx.x;
    if (i < N_NODES * 128) d_Bb[i] = __float2bfloat16(d_B[i]);
}

// ---------------- MMA helpers ----------------
__device__ __forceinline__ void ldsm4(uint32_t* r, const void* p) {
    unsigned a = (unsigned)__cvta_generic_to_shared(p);
    asm volatile("ldmatrix.sync.aligned.m8n8.x4.shared.b16 {%0,%1,%2,%3}, [%4];\n"
                 : "=r"(r[0]), "=r"(r[1]), "=r"(r[2]), "=r"(r[3]) : "r"(a));
}
__device__ __forceinline__ void ldsm4t(uint32_t* r, const void* p) {
    unsigned a = (unsigned)__cvta_generic_to_shared(p);
    asm volatile("ldmatrix.sync.aligned.m8n8.x4.trans.shared.b16 {%0,%1,%2,%3}, [%4];\n"
                 : "=r"(r[0]), "=r"(r[1]), "=r"(r[2]), "=r"(r[3]) : "r"(a));
}
__device__ __forceinline__ void mma_bf16(float* c, const uint32_t* a, uint32_t b0,
                                         uint32_t b1) {
    asm volatile(
        "mma.sync.aligned.m16n8k16.row.col.f32.bf16.bf16.f32 "
        "{%0,%1,%2,%3}, {%4,%5,%6,%7}, {%8,%9}, {%0,%1,%2,%3};\n"
        : "+f"(c[0]), "+f"(c[1]), "+f"(c[2]), "+f"(c[3])
        : "r"(a[0]), "r"(a[1]), "r"(a[2]), "r"(a[3]), "r"(b0), "r"(b1));
}
__device__ __forceinline__ void cp16(void* sdst, const void* gsrc, bool pred) {
    unsigned s = (unsigned)__cvta_generic_to_shared(sdst);
    int sz = pred ? 16 : 0;
    asm volatile("cp.async.cg.shared.global [%0], [%1], 16, %2;\n" ::"r"(s), "l"(gsrc),
                 "r"(sz));
}

// ---------------- unified TC GEMM, double-buffered, pre-split bf16 ----------------
__global__ __launch_bounds__(256) void gemm_tc(int asel, int wsel, int osel, int M,
                                               int N, int Kstride, int kcount) {
    const __nv_bfloat16 *Ah, *Al = nullptr, *Wh, *Wl;
    if (asel == 0) { Ah = d_xh; Al = d_xl; }
    else if (asel == 1) Ah = d_qb;
    else Ah = d_Bb;
    if (wsel == 0) { Wh = d_Wqh; Wl = d_Wql; }
    else if (wsel == 1) { Wh = d_Wgh; Wl = d_Wgl; }
    else { Wh = d_Werh; Wl = d_Werl; }
    const bool has_al = (asel == 0);

    extern __shared__ __align__(16) char dyn[];
    __nv_bfloat16* dynb = (__nv_bfloat16*)dyn;
    float* spool = (float*)(dyn + 59392);

    int tid = threadIdx.x, w = tid >> 5, l = tid & 31;
    int bm = blockIdx.y * 128, bn = blockIdx.x * 64;
    int wm = (w >> 1) * 32, wn = (w & 1) * 32;
    int kbeg = (wsel == 1) ? blockIdx.x * 512 : 0;
    if (osel == 2 && tid < 64) spool[tid] = 0.f;

    float acc[2][4][4];
#pragma unroll
    for (int a = 0; a < 2; a++)
#pragma unroll
        for (int b = 0; b < 4; b++)
#pragma unroll
            for (int c = 0; c < 4; c++) acc[a][b][c] = 0.f;

    int a_r = (l & 7) + ((l >> 3) & 1) * 8;
    int a_ko = ((l >> 4) & 1) * 8;

    auto pA = [&](int st, int p) { return dynb + (st * 2 + p) * 5120; };
    auto pW = [&](int st, int p) { return dynb + 20480 + (st * 2 + p) * 2304; };

    auto load_stage = [&](int st, int kc) {
        int nh = has_al ? 2 : 1;
        for (int p = 0; p < nh; p++) {
            const __nv_bfloat16* As = p ? Al : Ah;
            __nv_bfloat16* dst = pA(st, p);
#pragma unroll
            for (int i = 0; i < 2; i++) {
                int idx = tid + 256 * i;
                int row = idx >> 2, ch = idx & 3;
                int gr = bm + row;
                cp16(dst + row * 40 + ch * 8, As + (size_t)gr * Kstride + kc + ch * 8,
                     gr < M);
            }
        }
        for (int p = 0; p < 2; p++) {
            const __nv_bfloat16* Ws = p ? Wl : Wh;
            __nv_bfloat16* dst = pW(st, p);
            int k = tid >> 3, ch = tid & 7;
            cp16(dst + k * 72 + ch * 8, Ws + (size_t)(kc + k) * N + bn + ch * 8, true);
        }
        asm volatile("cp.async.commit_group;\n" ::);
    };

    auto compute = [&](int st) {
#pragma unroll
        for (int k16 = 0; k16 < 2; k16++) {
            uint32_t Af[2][4], Alf[2][4], Bhf[2][4], Blf[2][4];
            __nv_bfloat16* ah = pA(st, 0);
#pragma unroll
            for (int mt = 0; mt < 2; mt++)
                ldsm4(Af[mt], ah + (wm + mt * 16 + a_r) * 40 + k16 * 16 + a_ko);
            __nv_bfloat16* wh = pW(st, 0);
            __nv_bfloat16* wl = pW(st, 1);
#pragma unroll
            for (int p = 0; p < 2; p++) {
                ldsm4t(Bhf[p], wh + (k16 * 16 + a_r) * 72 + wn + p * 16 + a_ko);
                ldsm4t(Blf[p], wl + (k16 * 16 + a_r) * 72 + wn + p * 16 + a_ko);
            }
            if (has_al) {
                __nv_bfloat16* al = pA(st, 1);
#pragma unroll
                for (int mt = 0; mt < 2; mt++)
                    ldsm4(Alf[mt], al + (wm + mt * 16 + a_r) * 40 + k16 * 16 + a_ko);
            }
#pragma unroll
            for (int nt = 0; nt < 4; nt++) {
                uint32_t bh0 = Bhf[nt >> 1][(nt & 1) * 2], bh1 = Bhf[nt >> 1][(nt & 1) * 2 + 1];
                uint32_t bl0 = Blf[nt >> 1][(nt & 1) * 2], bl1 = Blf[nt >> 1][(nt & 1) * 2 + 1];
#pragma unroll
                for (int mt = 0; mt < 2; mt++) {
                    mma_bf16(acc[mt][nt], Af[mt], bh0, bh1);
                    mma_bf16(acc[mt][nt], Af[mt], bl0, bl1);
                    if (has_al) mma_bf16(acc[mt][nt], Alf[mt], bh0, bh1);
                }
            }
        }
    };

    int nIter = kcount >> 5;
    load_stage(0, kbeg);
    for (int it = 0; it < nIter; it++) {
        if (it + 1 < nIter) {
            load_stage((it + 1) & 1, kbeg + (it + 1) * 32);
            asm volatile("cp.async.wait_group 1;\n" ::);
        } else {
            asm volatile("cp.async.wait_group 0;\n" ::);
        }
        __syncthreads();
        compute(it & 1);
        __syncthreads();
    }

    int r0 = l >> 2, cq = (l & 3) * 2;
    if (osel == 0) {
        // region fixed per block (bn is a multiple of 64; regions are multiples of 1024)
        __nv_bfloat16* dstb = nullptr;
        float* dstf = nullptr;
        int coff;
        if (bn < 1024) { dstb = d_qb; coff = bn; }
        else if (bn < 2048) { dstb = d_kb; coff = bn - 1024; }
        else if (bn < 3072) { dstb = d_vb; coff = bn - 2048; }
        else { dstf = d_skip; coff = bn - 3072; }
#pragma unroll
        for (int mt = 0; mt < 2; mt++)
#pragma unroll
            for (int nt = 0; nt < 4; nt++) {
                int gcol = bn + wn + nt * 8 + cq;
                int col = coff + wn + nt * 8 + cq;
                float bb0 = d_biasc[gcol], bb1 = d_biasc[gcol + 1];
#pragma unroll
                for (int rr = 0; rr < 2; rr++) {
                    int row = bm + wm + mt * 16 + r0 + rr * 8;
                    if (row < M) {
                        float v0 = acc[mt][nt][rr * 2] + bb0;
                        float v1 = acc[mt][nt][rr * 2 + 1] + bb1;
                        if (dstf) {
                            dstf[row * 128 + col] = v0;
                            dstf[row * 128 + col + 1] = v1;
                        } else {
                            *(__nv_bfloat162*)&dstb[(size_t)row * HC + col] =
                                __floats2bfloat162_rn(v0, v1);
                        }
                    }
                }
            }
    } else if (osel == 1) {
#pragma unroll
        for (int mt = 0; mt < 2; mt++)
#pragma unroll
            for (int nt = 0; nt < 4; nt++) {
                int col = bn + wn + nt * 8 + cq;
#pragma unroll
                for (int rr = 0; rr < 2; rr++) {
                    int row = bm + wm + mt * 16 + r0 + rr * 8;
                    if (row < M) {
                        d_g[row * 128 + col] = acc[mt][nt][rr * 2];
                        d_g[row * 128 + col + 1] = acc[mt][nt][rr * 2 + 1];
                    }
                }
            }
    } else {
#pragma unroll
        for (int nt = 0; nt < 4; nt++) {
            int col = bn + wn + nt * 8 + cq;
            float s0 = 0.f, s1 = 0.f;
#pragma unroll
            for (int mt = 0; mt < 2; mt++)
#pragma unroll
                for (int rr = 0; rr < 2; rr++) {
                    int row = bm + wm + mt * 16 + r0 + rr * 8;
                    if (row < M) {
                        s0 += fmaxf(acc[mt][nt][rr * 2] + d_vout[row * 128 + col] +
                                        d_skip[row * 128 + col], 0.f);
                        s1 += fmaxf(acc[mt][nt][rr * 2 + 1] + d_vout[row * 128 + col + 1] +
                                        d_skip[row * 128 + col + 1], 0.f);
                    }
                }
#pragma unroll
            for (int off = 16; off >= 4; off >>= 1) {
                s0 += __shfl_xor_sync(0xffffffffu, s0, off);
                s1 += __shfl_xor_sync(0xffffffffu, s1, off);
            }
            if (l < 4) {
                atomicAdd(&spool[wn + nt * 8 + cq], s0);
                atomicAdd(&spool[wn + nt * 8 + cq + 1], s1);
            }
        }
        __syncthreads();
        if (tid < 64) atomicAdd(&d_pooled[bn + tid], spool[tid]);
    }
}

// ---------------- edge pass A: alpha (quad-per-head, LDG.128) ----------------
__device__ __forceinline__ float dot8(uint4 a, uint4 b) {
    float2 a0 = __bfloat1622float2(*(__nv_bfloat162*)&a.x);
    float2 a1 = __bfloat1622float2(*(__nv_bfloat162*)&a.y);
    float2 a2 = __bfloat1622float2(*(__nv_bfloat162*)&a.z);
    float2 a3 = __bfloat1622float2(*(__nv_bfloat162*)&a.w);
    float2 b0 = __bfloat1622float2(*(__nv_bfloat162*)&b.x);
    float2 b1 = __bfloat1622float2(*(__nv_bfloat162*)&b.y);
    float2 b2 = __bfloat1622float2(*(__nv_bfloat162*)&b.z);
    float2 b3 = __bfloat1622float2(*(__nv_bfloat162*)&b.w);
    return a0.x * b0.x + a0.y * b0.y + a1.x * b1.x + a1.y * b1.y + a2.x * b2.x +
           a2.y * b2.y + a3.x * b3.x + a3.y * b3.y;
}

__global__ __launch_bounds__(256) void edge_alpha(const float* __restrict__ ea,
                                                  const int* __restrict__ eidx) {
    int e = blockIdx.x * 8 + threadIdx.y;
    if (e >= N_EDGES) return;
    int l = threadIdx.x;
    int src = __ldg(&eidx[e]);
    int dst = __ldg(&eidx[N_EDGES + e]);
    int h = l >> 2, p = l & 3;
    const uint4* q4 = (const uint4*)&d_qb[(size_t)dst * HC + h * 128 + p * 32];
    const uint4* k4 = (const uint4*)&d_kb[(size_t)src * HC + h * 128 + p * 32];
    uint4 qa0 = q4[0], qa1 = q4[1], qa2 = q4[2], qa3 = q4[3];
    uint4 kb0 = k4[0], kb1 = k4[1], kb2 = k4[2], kb3 = k4[3];
    float4 g4 = *(const float4*)&d_g[dst * 128 + h * 16 + p * 4];
    float4 e4 = *(const float4*)&ea[e * F_EDGE + p * 4];
    float dp = dot8(qa0, kb0) + dot8(qa1, kb1) + dot8(qa2, kb2) + dot8(qa3, kb3);
    dp += g4.x * e4.x + g4.y * e4.y + g4.z * e4.z + g4.w * e4.w;
    dp += __shfl_xor_sync(0xffffffffu, dp, 1);
    dp += __shfl_xor_sync(0xffffffffu, dp, 2);
    if (p == 0) {
        float aex = __expf(dp * 0.08838834764831845f);
        d_aexp[e * 8 + h] = aex;
        atomicAdd(&d_s[dst * 8 + h], aex);
    }
}

// ---------------- edge pass B: v-term (LDG.128) + B scatter ----------------
__global__ __launch_bounds__(256) void edge_msg(const float* __restrict__ ea,
                                                const int* __restrict__ eidx) {
    int e = blockIdx.x * 8 + threadIdx.y;
    if (e >= N_EDGES) return;
    int l = threadIdx.x;
    int src = __ldg(&eidx[e]);
    int dst = __ldg(&eidx[N_EDGES + e]);
    float an = 0.f;
    if (l < 8) {
        float s = d_s[dst * 8 + l];
        an = 0.125f * d_aexp[e * 8 + l] / (s + 1e-16f);
    }
    int h2 = l >> 4, c8 = l & 15;
    float acc[8];
#pragma unroll
    for (int j = 0; j < 8; j++) acc[j] = 0.f;
#pragma unroll
    for (int hh = 0; hh < 4; hh++) {
        int h = h2 * 4 + hh;
        float anh = __shfl_sync(0xffffffffu, an, h);
        uint4 vv = *(const uint4*)&d_vb[(size_t)src * HC + h * 128 + c8 * 8];
        float2 v0 = __bfloat1622float2(*(__nv_bfloat162*)&vv.x);
        float2 v1 = __bfloat1622float2(*(__nv_bfloat162*)&vv.y);
        float2 v2 = __bfloat1622float2(*(__nv_bfloat162*)&vv.z);
        float2 v3 = __bfloat1622float2(*(__nv_bfloat162*)&vv.w);
        acc[0] += anh * v0.x;
        acc[1] += anh * v0.y;
        acc[2] += anh * v1.x;
        acc[3] += anh * v1.y;
        acc[4] += anh * v2.x;
        acc[5] += anh * v2.y;
        acc[6] += anh * v3.x;
        acc[7] += anh * v3.y;
    }
#pragma unroll
    for (int j = 0; j < 8; j++) acc[j] += __shfl_xor_sync(0xffffffffu, acc[j], 16);
    if (h2 == 0) {
        float* outp = &d_vout[dst * 128 + c8 * 8];
        asm volatile("red.global.add.v4.f32 [%0], {%1,%2,%3,%4};\n" ::"l"(outp),
                     "f"(acc[0]), "f"(acc[1]), "f"(acc[2]), "f"(acc[3])
                     : "memory");
        asm volatile("red.global.add.v4.f32 [%0], {%1,%2,%3,%4};\n" ::"l"(outp + 4),
                     "f"(acc[4]), "f"(acc[5]), "f"(acc[6]), "f"(acc[7])
                     : "memory");
    }
    float4 ea4 = ((const float4*)&ea[e * F_EDGE])[l & 3];
    float anj = __shfl_sync(0xffffffffu, an, l >> 2);
    float* bp = &d_B[dst * 128 + l * 4];
    asm volatile("red.global.add.v4.f32 [%0], {%1,%2,%3,%4};\n" ::"l"(bp),
                 "f"(anj * ea4.x), "f"(anj * ea4.y), "f"(anj * ea4.z), "f"(anj * ea4.w)
                 : "memory");
}

// ---------------- final dot ----------------
__global__ __launch_bounds__(128) void final_dot(const float* __restrict__ Wd,
                                                 const float* __restrict__ bd,
                                                 float* __restrict__ out) {
    int t = threadIdx.x;
    float v = d_pooled[t] * Wd[t];
#pragma unroll
    for (int o = 16; o; o >>= 1) v += __shfl_xor_sync(0xffffffffu, v, o);
    __shared__ float red[4];
    if ((t & 31) == 0) red[t >> 5] = v;
    __syncthreads();
    if (t == 0) out[0] = red[0] + red[1] + red[2] + red[3] + bd[0];
}

extern "C" void kernel_launch(void* const* d_in, const int* in_sizes, int n_in,
                              void* d_out, int out_size) {
    const float* x          = (const float*)d_in[0];
    const float* edge_attr  = (const float*)d_in[1];
    const int*   edge_index = (const int*)d_in[2];
    const float* Wq = (const float*)d_in[3];
    const float* bq = (const float*)d_in[4];
    const float* Wk = (const float*)d_in[5];
    const float* bk = (const float*)d_in[6];
    const float* Wv = (const float*)d_in[7];
    const float* bv = (const float*)d_in[8];
    const float* We = (const float*)d_in[9];
    const float* Wskip = (const float*)d_in[10];
    const float* bskip = (const float*)d_in[11];
    const float* Wd = (const float*)d_in[12];
    const float* bd = (const float*)d_in[13];
    float* out = (float*)d_out;

    static void *p_vout = nullptr, *p_B = nullptr, *p_s = nullptr, *p_pooled = nullptr;
    if (!p_vout) {
        cudaFuncSetAttribute(gemm_tc, cudaFuncAttributeMaxDynamicSharedMemorySize, 60416);
        cudaGetSymbolAddress(&p_vout, d_vout);
        cudaGetSymbolAddress(&p_B, d_B);
        cudaGetSymbolAddress(&p_s, d_s);
        cudaGetSymbolAddress(&p_pooled, d_pooled);
    }

    cudaMemsetAsync(p_vout, 0, N_NODES * 128 * sizeof(float), 0);
    cudaMemsetAsync(p_B, 0, N_NODES * 128 * sizeof(float), 0);
    cudaMemsetAsync(p_s, 0, N_NODES * HEADS * sizeof(float), 0);
    cudaMemsetAsync(p_pooled, 0, 128 * sizeof(float), 0);

    prep_all<<<(PREP_TOTAL + 255) / 256, 256>>>(x, Wq, Wk, Wv, Wskip, bq, bk, bv, bskip,
                                                We);

    // fused q|k|v|skip : [10000,128] @ [128,3200]
    gemm_tc<<<dim3(50, 79), 256, 59648>>>(0, 0, 0, N_NODES, NQKVS, 128, 128);
    // g = q @ Wg (block-diag: each n-block uses its 512-wide k-slice)
    gemm_tc<<<dim3(2, 79), 256, 59648>>>(1, 1, 1, N_NODES, 128, 1024, 512);

    dim3 eblk(32, 8);
    edge_alpha<<<12500, eblk>>>(edge_attr, edge_index);
    edge_msg<<<12500, eblk>>>(edge_attr, edge_index);

    split_B<<<5000, 256>>>();
    // eterm = B @ Wer, fused relu(eterm+vout+skip) column-sum into pooled
    gemm_tc<<<dim3(2, 79), 256, 59648>>>(2, 2, 2, N_NODES, 128, 128, 128);

    final_dot<<<1, 128>>>(Wd, bd, out);
}